// round 8
// baseline (speedup 1.0000x reference)
#include <cuda_runtime.h>
#include <math.h>

#define E 64
#define CHUNK 64                       // tokens per routing chunk
#define MAX_TOK 16384
#define MAX_CHUNKS (MAX_TOK / CHUNK)   // 256
#define CPQ 64                         // chunks per quarter-group in prefix

// Scratch (no allocations allowed)
__device__ int   g_idx[MAX_TOK];
__device__ float g_gate[MAX_TOK];
__device__ int   g_slot[MAX_TOK];
__device__ int   g_hist[MAX_CHUNKS * E];
__device__ int   g_base[MAX_CHUNKS * E];
__device__ int   g_done = 0;           // self-resetting per launch

// ---------------------------------------------------------------------------
// Kernel A: routing (grid = nchunks blocks x 256 threads) + last-arriving
// block computes the cross-chunk exclusive prefix and ALL per-token slots.
// Small kernel; runs concurrently with kernel B via PDL.
// ---------------------------------------------------------------------------
__global__ void route_slot_kernel(const float* __restrict__ in,
                                  int s, int nchunks, int cap) {
    __shared__ int hist[E];
    __shared__ int seg_sh[4][E];
    __shared__ int cnt_sh[8][E];
    __shared__ int is_last;

    int b   = blockIdx.x;
    int tid = threadIdx.x;             // 0..255

    // ---- route chunk b ----
    if (tid < E) hist[tid] = 0;

    int t_local = tid >> 2;            // token within chunk 0..63
    int quad    = tid & 3;             // 16-expert slice
    int token   = b * CHUNK + t_local;
    bool valid  = (token < s);
    int  tok_c  = valid ? token : (s - 1);

    const float4* p4 = (const float4*)(in + (size_t)tok_c * E + quad * 16);
    float4 va = p4[0], vb = p4[1], vc = p4[2], vd = p4[3];
    float v[16] = {va.x, va.y, va.z, va.w, vb.x, vb.y, vb.z, vb.w,
                   vc.x, vc.y, vc.z, vc.w, vd.x, vd.y, vd.z, vd.w};

    float m = v[0];
    int   am = quad * 16;
#pragma unroll
    for (int k = 1; k < 16; k++)
        if (v[k] > m) { m = v[k]; am = quad * 16 + k; }
#pragma unroll
    for (int off = 1; off < 4; off <<= 1) {
        float mo = __shfl_xor_sync(0xffffffffu, m, off);
        int   ao = __shfl_xor_sync(0xffffffffu, am, off);
        if (mo > m || (mo == m && ao < am)) { m = mo; am = ao; }
    }
    float sum = 0.f;
#pragma unroll
    for (int k = 0; k < 16; k++) sum += __expf(v[k] - m);
#pragma unroll
    for (int off = 1; off < 4; off <<= 1)
        sum += __shfl_xor_sync(0xffffffffu, sum, off);

    __syncthreads();                   // hist zeroed
    if (valid && quad == 0) {
        g_idx[token]  = am;
        g_gate[token] = 1.0f / sum;
        atomicAdd(&hist[am], 1);
    }
    __syncthreads();
    if (tid < E) g_hist[b * E + tid] = hist[tid];
    __threadfence();                   // publish g_hist/g_idx/g_gate
    if (tid == 0)
        is_last = (atomicAdd(&g_done, 1) == nchunks - 1) ? 1 : 0;
    __syncthreads();

    if (!is_last) return;

    // ---- last block: prefix + all slots ----
    if (tid == 0) atomicExch(&g_done, 0);     // reset for next replay
    __threadfence();                          // acquire all g_hist/g_idx

    int e = tid & 63;
    int q = tid >> 6;                         // 0..3
    int run = 0;
#pragma unroll 4
    for (int j = 0; j < CPQ; j++) {
        int c = q * CPQ + j;
        run += (c < nchunks) ? g_hist[c * E + e] : 0;
    }
    seg_sh[q][e] = run;
    __syncthreads();
    int seg = 0;
    for (int qq = 0; qq < q; qq++) seg += seg_sh[qq][e];
    int base_run = seg;
    for (int j = 0; j < CPQ; j++) {
        int c = q * CPQ + j;
        if (c < nchunks) {
            g_base[c * E + e] = base_run;
            base_run += g_hist[c * E + e];
        }
    }
    __syncthreads();

    int w    = tid >> 5;
    int lane = tid & 31;
    for (int c = w; c < nchunks; c += 8) {
        cnt_sh[w][lane]      = 0;
        cnt_sh[w][lane + 32] = 0;
        __syncwarp();
        int cbase = c * CHUNK;
#pragma unroll
        for (int p = 0; p < 2; p++) {
            int t  = cbase + p * 32 + lane;
            int ee = (t < s) ? g_idx[t] : -1;
            unsigned mk = __match_any_sync(0xffffffffu, ee);
            int within  = __popc(mk & ((1u << lane) - 1));
            int carry   = (p == 1 && ee >= 0) ? cnt_sh[w][ee] : 0;
            if (p == 0 && ee >= 0 && within == 0)
                cnt_sh[w][ee] = __popc(mk);
            __syncwarp();
            if (t < s && ee >= 0) {
                int r = g_base[c * E + ee] + carry + within;
                g_slot[t] = (r < cap) ? (ee * cap + r) : -1;
            }
        }
    }
    // g_slot visibility to kernel B is guaranteed by PDL's default
    // completion trigger (fires when this grid fully completes).
}

// ---------------------------------------------------------------------------
// Kernel B: fill + fix-up, launched with PDL so its zeroing overlaps
// kernel A. NO threadfence (the R7 killer). Grid = s blocks x 256.
// ---------------------------------------------------------------------------
__global__ void fill_fix_kernel(float* __restrict__ out, size_t sec, int row,
                                int write_mask) {
    int b   = blockIdx.x;
    int tid = threadIdx.x;

    int n4 = row >> 2;
    float4* __restrict__ c4 = (float4*)(out + (size_t)b * row);
    float4* __restrict__ m4 = (float4*)(out + sec + (size_t)b * row);
    float4 z = make_float4(0.f, 0.f, 0.f, 0.f);

    if (write_mask) {
        for (int i = tid; i < n4; i += blockDim.x) {
            __stcs(&c4[i], z);
            __stcs(&m4[i], z);
        }
    } else {
        for (int i = tid; i < n4; i += blockDim.x)
            __stcs(&c4[i], z);
    }
    __syncthreads();                  // zero stores ordered before fixup

    if (tid == 0) {
        cudaGridDependencySynchronize();   // wait for kernel A completion
        int p = g_slot[b];
        if (p >= 0) {
            out[(size_t)b * row + (size_t)p] = g_gate[b];
            if (write_mask) out[sec + (size_t)b * row + (size_t)p] = 1.0f;
        }
    }
}

// ---------------------------------------------------------------------------
// Tail: zero anything beyond the two tensors (output poisoned 0xAA)
// ---------------------------------------------------------------------------
__global__ void tail_zero(float* __restrict__ out, size_t start, size_t end) {
    size_t i = start + blockIdx.x * (size_t)blockDim.x + threadIdx.x;
    size_t stride = gridDim.x * (size_t)blockDim.x;
    for (; i < end; i += stride) out[i] = 0.f;
}

// ---------------------------------------------------------------------------
extern "C" void kernel_launch(void* const* d_in, const int* in_sizes, int n_in,
                              void* d_out, int out_size) {
    const float* in = (const float*)d_in[0];
    float* out = (float*)d_out;

    int total = in_sizes[0];
    int s = total / E;
    int cap = (int)floor(1.25 * (double)s / (double)E);
    cap += (cap & 1);
    if (cap < 4) cap = 4;

    int row = E * cap;
    size_t sec = (size_t)s * (size_t)row;
    int write_mask = ((size_t)out_size >= 2 * sec) ? 1 : 0;

    int nchunks = (s + CHUNK - 1) / CHUNK;

    // A) routing + prefix + slots (small)
    route_slot_kernel<<<nchunks, 256>>>(in, s, nchunks, cap);

    // B) fill + fixup, overlapped with A via programmatic dependent launch
    {
        cudaLaunchConfig_t cfg = {};
        cfg.gridDim  = dim3((unsigned)s, 1, 1);
        cfg.blockDim = dim3(256, 1, 1);
        cfg.dynamicSmemBytes = 0;
        cfg.stream = 0;
        cudaLaunchAttribute at[1];
        at[0].id = cudaLaunchAttributeProgrammaticStreamSerialization;
        at[0].val.programmaticStreamSerializationAllowed = 1;
        cfg.attrs = at;
        cfg.numAttrs = 1;
        cudaLaunchKernelEx(&cfg, fill_fix_kernel, out, sec, row, write_mask);
    }

    // C) tail beyond 2*sec, if any
    size_t covered = write_mask ? 2 * sec : sec;
    if ((size_t)out_size > covered) {
        tail_zero<<<256, 256>>>(out, covered, (size_t)out_size);
    }
}

// round 9
// speedup vs baseline: 1.0008x; 1.0008x over previous
#include <cuda_runtime.h>
#include <math.h>

#define E 64
#define CHUNK 64                       // tokens per routing chunk
#define MAX_TOK 16384
#define MAX_CHUNKS (MAX_TOK / CHUNK)   // 256
#define CPQ 64                         // chunks per quarter-group in prefix

// Scratch (no allocations allowed)
__device__ int   g_idx[MAX_TOK];
__device__ float g_gate[MAX_TOK];
__device__ int   g_slot[MAX_TOK];
__device__ int   g_hist[MAX_CHUNKS * E];
__device__ int   g_base[MAX_CHUNKS * E];
__device__ int   g_done = 0;           // self-resetting per launch

// ---------------------------------------------------------------------------
// Mega kernel. grid = s blocks x 256 threads.
//  * blocks b < nchunks: route chunk b; LAST-arriving routing block also
//    computes the cross-chunk prefix + all slots (hidden under the fill
//    storm of the other ~8k blocks).
//  * all blocks: zero-stream token b's rows and exit. NO fence, NO spin,
//    NO fixup in the tail (R7's bandwidth killer).
// ---------------------------------------------------------------------------
__global__ void mega_kernel(const float* __restrict__ in,
                            float* __restrict__ out,
                            size_t sec, int row, int s, int nchunks,
                            int cap, int write_mask) {
    __shared__ int hist[E];
    __shared__ int seg_sh[4][E];
    __shared__ int cnt_sh[8][E];
    __shared__ int is_last;

    int b   = blockIdx.x;
    int tid = threadIdx.x;             // 0..255

    // ================= routing phase (first nchunks blocks) =================
    if (b < nchunks) {
        if (tid < E) hist[tid] = 0;

        int t_local = tid >> 2;        // token within chunk 0..63
        int quad    = tid & 3;         // 16-expert slice
        int token   = b * CHUNK + t_local;
        bool valid  = (token < s);
        int  tok_c  = valid ? token : (s - 1);

        const float4* p4 = (const float4*)(in + (size_t)tok_c * E + quad * 16);
        float4 va = p4[0], vb = p4[1], vc = p4[2], vd = p4[3];
        float v[16] = {va.x, va.y, va.z, va.w, vb.x, vb.y, vb.z, vb.w,
                       vc.x, vc.y, vc.z, vc.w, vd.x, vd.y, vd.z, vd.w};

        float m = v[0];
        int   am = quad * 16;
#pragma unroll
        for (int k = 1; k < 16; k++)
            if (v[k] > m) { m = v[k]; am = quad * 16 + k; }
#pragma unroll
        for (int off = 1; off < 4; off <<= 1) {
            float mo = __shfl_xor_sync(0xffffffffu, m, off);
            int   ao = __shfl_xor_sync(0xffffffffu, am, off);
            if (mo > m || (mo == m && ao < am)) { m = mo; am = ao; }
        }
        float sum = 0.f;
#pragma unroll
        for (int k = 0; k < 16; k++) sum += __expf(v[k] - m);
#pragma unroll
        for (int off = 1; off < 4; off <<= 1)
            sum += __shfl_xor_sync(0xffffffffu, sum, off);

        __syncthreads();               // hist zeroed
        if (valid && quad == 0) {
            g_idx[token]  = am;
            g_gate[token] = 1.0f / sum;
            atomicAdd(&hist[am], 1);
        }
        __syncthreads();
        if (tid < E) g_hist[b * E + tid] = hist[tid];
        __threadfence();               // publish g_hist/g_idx (128 blocks only)
        if (tid == 0)
            is_last = (atomicAdd(&g_done, 1) == nchunks - 1) ? 1 : 0;
        __syncthreads();

        // ===== last routing block: prefix + all slots (hidden under fill) ===
        if (is_last) {
            if (tid == 0) atomicExch(&g_done, 0);   // reset for next replay
            __threadfence();                        // acquire g_hist/g_idx

            // cross-chunk exclusive prefix, 4 thread-groups x 64 experts
            int e = tid & 63;
            int q = tid >> 6;                       // 0..3
            int run = 0;
#pragma unroll 4
            for (int j = 0; j < CPQ; j++) {
                int c = q * CPQ + j;
                run += (c < nchunks) ? g_hist[c * E + e] : 0;
            }
            seg_sh[q][e] = run;
            __syncthreads();
            int seg = 0;
            for (int qq = 0; qq < q; qq++) seg += seg_sh[qq][e];
            int base_run = seg;
            for (int j = 0; j < CPQ; j++) {
                int c = q * CPQ + j;
                if (c < nchunks) {
                    g_base[c * E + e] = base_run;
                    base_run += g_hist[c * E + e];
                }
            }
            __syncthreads();

            // per-token in-chunk rank via match_any; 8 warps, 1 chunk each
            int w    = tid >> 5;
            int lane = tid & 31;
            for (int c = w; c < nchunks; c += 8) {
                cnt_sh[w][lane]      = 0;
                cnt_sh[w][lane + 32] = 0;
                __syncwarp();
                int cbase = c * CHUNK;
#pragma unroll
                for (int p = 0; p < 2; p++) {
                    int t  = cbase + p * 32 + lane;
                    int ee = (t < s) ? g_idx[t] : -1;
                    unsigned mk = __match_any_sync(0xffffffffu, ee);
                    int within  = __popc(mk & ((1u << lane) - 1));
                    int carry   = (p == 1 && ee >= 0) ? cnt_sh[w][ee] : 0;
                    if (p == 0 && ee >= 0 && within == 0)
                        cnt_sh[w][ee] = __popc(mk);
                    __syncwarp();
                    if (t < s && ee >= 0) {
                        int r = g_base[c * E + ee] + carry + within;
                        g_slot[t] = (r < cap) ? (ee * cap + r) : -1;
                    }
                }
            }
            // visibility of g_slot to the next kernel: kernel boundary.
        }
    }

    // ======================= fill phase (all blocks) ========================
    int n4 = row >> 2;
    float4* __restrict__ c4 = (float4*)(out + (size_t)b * row);
    float4* __restrict__ m4 = (float4*)(out + sec + (size_t)b * row);
    float4 z = make_float4(0.f, 0.f, 0.f, 0.f);

    if (write_mask) {
        for (int i = tid; i < n4; i += blockDim.x) {
            __stcs(&c4[i], z);
            __stcs(&m4[i], z);
        }
    } else {
        for (int i = tid; i < n4; i += blockDim.x)
            __stcs(&c4[i], z);
    }
    // exit — no fence, no spin, no fixup
}

// ---------------------------------------------------------------------------
// Scatter fix-up: one thread per token, two fire-and-forget stores.
// Ordered after mega by the kernel boundary.
// ---------------------------------------------------------------------------
__global__ void scatter_fix_kernel(float* __restrict__ out, size_t sec,
                                   int row, int s, int write_mask) {
    int t = blockIdx.x * blockDim.x + threadIdx.x;
    if (t < s) {
        int p = g_slot[t];
        if (p >= 0) {
            size_t off = (size_t)t * row + (size_t)p;
            out[off] = g_gate[t];
            if (write_mask) out[sec + off] = 1.0f;
        }
    }
}

// ---------------------------------------------------------------------------
// Tail: zero anything beyond the two tensors (output poisoned 0xAA)
// ---------------------------------------------------------------------------
__global__ void tail_zero(float* __restrict__ out, size_t start, size_t end) {
    size_t i = start + blockIdx.x * (size_t)blockDim.x + threadIdx.x;
    size_t stride = gridDim.x * (size_t)blockDim.x;
    for (; i < end; i += stride) out[i] = 0.f;
}

// ---------------------------------------------------------------------------
extern "C" void kernel_launch(void* const* d_in, const int* in_sizes, int n_in,
                              void* d_out, int out_size) {
    const float* in = (const float*)d_in[0];
    float* out = (float*)d_out;

    int total = in_sizes[0];
    int s = total / E;
    int cap = (int)floor(1.25 * (double)s / (double)E);
    cap += (cap & 1);
    if (cap < 4) cap = 4;

    int row = E * cap;
    size_t sec = (size_t)s * (size_t)row;
    int write_mask = ((size_t)out_size >= 2 * sec) ? 1 : 0;

    int nchunks = (s + CHUNK - 1) / CHUNK;

    // 1) fill + routing + (hidden) prefix/slots
    mega_kernel<<<s, 256>>>(in, out, sec, row, s, nchunks, cap, write_mask);

    // 2) tiny fix-up scatter
    scatter_fix_kernel<<<(s + 255) / 256, 256>>>(out, sec, row, s, write_mask);

    // 3) tail beyond 2*sec, if any
    size_t covered = write_mask ? 2 * sec : sec;
    if ((size_t)out_size > covered) {
        tail_zero<<<256, 256>>>(out, covered, (size_t)out_size);
    }
}

// round 10
// speedup vs baseline: 1.1462x; 1.1453x over previous
#include <cuda_runtime.h>
#include <math.h>

#define E 64
#define CHUNK 64                       // tokens per routing chunk
#define MAX_TOK 16384
#define MAX_CHUNKS (MAX_TOK / CHUNK)

// Scratch (no allocations allowed)
__device__ int   g_idx[MAX_TOK];
__device__ float g_gate[MAX_TOK];
__device__ int   g_slot[MAX_TOK];
__device__ int   g_hist[MAX_CHUNKS * E];

// ---------------------------------------------------------------------------
// K1: zero the MASK tensor + embedded routing.
// Every block zero-streams token b's row of the mask tensor (E*cap floats).
// Blocks b < nchunks first route chunk b (4 threads/token); this work hides
// under the DRAM-saturated store stream of the other ~8k blocks (R6-proven).
// ---------------------------------------------------------------------------
__global__ void fill_mask_route_kernel(const float* __restrict__ in,
                                       float* __restrict__ out,
                                       size_t sec, int row, int s,
                                       int nchunks, int write_mask) {
    __shared__ int hist[E];

    int b   = blockIdx.x;
    int tid = threadIdx.x;             // 0..255

    if (b < nchunks) {
        if (tid < E) hist[tid] = 0;

        int t_local = tid >> 2;        // token within chunk 0..63
        int quad    = tid & 3;         // 16-expert slice
        int token   = b * CHUNK + t_local;
        bool valid  = (token < s);
        int  tok_c  = valid ? token : (s - 1);

        const float4* p4 = (const float4*)(in + (size_t)tok_c * E + quad * 16);
        float4 va = p4[0], vb = p4[1], vc = p4[2], vd = p4[3];
        float v[16] = {va.x, va.y, va.z, va.w, vb.x, vb.y, vb.z, vb.w,
                       vc.x, vc.y, vc.z, vc.w, vd.x, vd.y, vd.z, vd.w};

        float m = v[0];
        int   am = quad * 16;
#pragma unroll
        for (int k = 1; k < 16; k++)
            if (v[k] > m) { m = v[k]; am = quad * 16 + k; }
#pragma unroll
        for (int off = 1; off < 4; off <<= 1) {
            float mo = __shfl_xor_sync(0xffffffffu, m, off);
            int   ao = __shfl_xor_sync(0xffffffffu, am, off);
            if (mo > m || (mo == m && ao < am)) { m = mo; am = ao; }
        }
        float sum = 0.f;
#pragma unroll
        for (int k = 0; k < 16; k++) sum += __expf(v[k] - m);
#pragma unroll
        for (int off = 1; off < 4; off <<= 1)
            sum += __shfl_xor_sync(0xffffffffu, sum, off);

        __syncthreads();               // hist zeroed
        if (valid && quad == 0) {
            g_idx[token]  = am;
            g_gate[token] = 1.0f / sum;
            atomicAdd(&hist[am], 1);
        }
        __syncthreads();
        if (tid < E) g_hist[b * E + tid] = hist[tid];
        // visibility to K2: kernel boundary. No fence.
    }

    // zero this token's MASK row (combine row handled by K3)
    float* base = out + (write_mask ? sec : 0) + (size_t)b * row;
    float4* __restrict__ d4 = (float4*)base;
    int n4 = row >> 2;
    float4 z = make_float4(0.f, 0.f, 0.f, 0.f);
    for (int i = tid; i < n4; i += blockDim.x)
        __stcs(&d4[i], z);
}

// ---------------------------------------------------------------------------
// K2: cross-chunk exclusive prefix + in-chunk rank -> g_slot (R3-proven).
// grid = nchunks, 128 threads; full hist table in dynamic smem.
// ---------------------------------------------------------------------------
__global__ void prefix_slot_kernel(int s, int cap, int nchunks) {
    extern __shared__ int hist_sh[];          // nchunks * E ints (32 KB)
    __shared__ int base_sh[E];
    __shared__ int idx_sh[CHUNK];
    __shared__ int w0cnt[E];

    int blk = blockIdx.x;
    int tid = threadIdx.x;                    // 0..127

    int total = nchunks * E;
    for (int i = tid; i < total; i += 128) hist_sh[i] = g_hist[i];
    if (tid < E) w0cnt[tid] = 0;

    int base = blk * CHUNK;
    int tokens = s - base;
    if (tokens > CHUNK) tokens = CHUNK;
    if (tid < tokens) idx_sh[tid] = g_idx[base + tid];
    __syncthreads();

    if (tid < E) {
        int r = 0;
        for (int c = 0; c < blk; c++) r += hist_sh[c * E + tid];
        base_sh[tid] = r;
    }
    __syncthreads();

    int e = (tid < tokens) ? idx_sh[tid] : -1;
    unsigned mask = __match_any_sync(0xffffffffu, e);
    int lane   = tid & 31;
    int within = __popc(mask & ((1u << lane) - 1));
    if (tid < 32 && within == 0 && e >= 0) w0cnt[e] = __popc(mask);
    __syncthreads();

    if (tid < tokens && e >= 0) {
        int r = base_sh[e] + within + ((tid >= 32) ? w0cnt[e] : 0);
        g_slot[base + tid] = (r < cap) ? (e * cap + r) : -1;
    }
}

// ---------------------------------------------------------------------------
// K3: zero the COMBINE tensor + in-block fix-up of BOTH tensors.
// Combine fix-up hits a line this block just wrote (store-buffer/L2 hot:
// free). Mask fix-up is one scattered store whose latency hides under the
// surrounding 46us of streaming stores.
// ---------------------------------------------------------------------------
__global__ void fill_combine_fix_kernel(float* __restrict__ out, size_t sec,
                                        int row, int write_mask) {
    int b   = blockIdx.x;
    int tid = threadIdx.x;

    float4* __restrict__ c4 = (float4*)(out + (size_t)b * row);
    int n4 = row >> 2;
    float4 z = make_float4(0.f, 0.f, 0.f, 0.f);
    for (int i = tid; i < n4; i += blockDim.x)
        __stcs(&c4[i], z);
    __syncthreads();                   // order zeros before fixup (same block)

    if (tid == 0) {
        int p = g_slot[b];
        if (p >= 0) {
            out[(size_t)b * row + (size_t)p] = g_gate[b];
            if (write_mask) out[sec + (size_t)b * row + (size_t)p] = 1.0f;
        }
    }
}

// ---------------------------------------------------------------------------
// Tail: zero anything beyond the two tensors (output poisoned 0xAA)
// ---------------------------------------------------------------------------
__global__ void tail_zero(float* __restrict__ out, size_t start, size_t end) {
    size_t i = start + blockIdx.x * (size_t)blockDim.x + threadIdx.x;
    size_t stride = gridDim.x * (size_t)blockDim.x;
    for (; i < end; i += stride) out[i] = 0.f;
}

// ---------------------------------------------------------------------------
extern "C" void kernel_launch(void* const* d_in, const int* in_sizes, int n_in,
                              void* d_out, int out_size) {
    const float* in = (const float*)d_in[0];
    float* out = (float*)d_out;

    int total = in_sizes[0];
    int s = total / E;
    int cap = (int)floor(1.25 * (double)s / (double)E);
    cap += (cap & 1);
    if (cap < 4) cap = 4;

    int row = E * cap;
    size_t sec = (size_t)s * (size_t)row;
    int write_mask = ((size_t)out_size >= 2 * sec) ? 1 : 0;

    int nchunks = (s + CHUNK - 1) / CHUNK;

    // K1: zero mask tensor + embedded routing (route hidden under stores)
    fill_mask_route_kernel<<<s, 256>>>(in, out, sec, row, s, nchunks,
                                       write_mask);

    // K2: prefix + slots (~1.5us, the only exposed prologue piece)
    size_t smem_bytes = (size_t)nchunks * E * sizeof(int);
    if (smem_bytes > 48 * 1024) {
        cudaFuncSetAttribute(prefix_slot_kernel,
                             cudaFuncAttributeMaxDynamicSharedMemorySize,
                             (int)smem_bytes);
    }
    prefix_slot_kernel<<<nchunks, 128, smem_bytes>>>(s, cap, nchunks);

    // K3: zero combine tensor + in-block fixup of both tensors
    fill_combine_fix_kernel<<<s, 256>>>(out, sec, row, write_mask);

    // tail beyond 2*sec, if any
    size_t covered = write_mask ? 2 * sec : sec;
    if ((size_t)out_size > covered) {
        tail_zero<<<256, 256>>>(out, covered, (size_t)out_size);
    }
}